// round 14
// baseline (speedup 1.0000x reference)
#include <cuda_runtime.h>

#define HDIM   128
#define NSTEPS 60
#define SB     64      // samples per block
#define NTHR   512
#define CPAD   32      // cur row length in u64 pairs

typedef unsigned long long u64;
typedef ulonglong2 ull2;

__device__ __forceinline__ u64 pack2(float a, float b) {
    u64 r; asm("mov.b64 %0, {%1, %2};" : "=l"(r) : "f"(a), "f"(b)); return r;
}
__device__ __forceinline__ float2 unpack2(u64 v) {
    float2 r; asm("mov.b64 {%0, %1}, %2;" : "=f"(r.x), "=f"(r.y) : "l"(v)); return r;
}
__device__ __forceinline__ u64 ffma2(u64 a, u64 b, u64 c) {
    u64 d; asm("fma.rn.f32x2 %0, %1, %2, %3;" : "=l"(d) : "l"(a), "l"(b), "l"(c)); return d;
}
__device__ __forceinline__ u64 fmul2(u64 a, u64 b) {
    u64 d; asm("mul.rn.f32x2 %0, %1, %2;" : "=l"(d) : "l"(a), "l"(b)); return d;
}
__device__ __forceinline__ u64 fadd2(u64 a, u64 b) {
    u64 d; asm("add.rn.f32x2 %0, %1, %2;" : "=l"(d) : "l"(a), "l"(b)); return d;
}
__device__ __forceinline__ void silu2(u64 z, u64& h, u64& d) {
    float2 zf = unpack2(z);
    float e0 = __expf(-zf.x), e1 = __expf(-zf.y);
    float s0 = 1.0f / (1.0f + e0), s1 = 1.0f / (1.0f + e1);
    float h0 = zf.x * s0,          h1 = zf.y * s1;
    float d0 = fmaf(h0, 1.0f - s0, s0);
    float d1 = fmaf(h1, 1.0f - s1, s1);
    h = pack2(h0, h1);
    d = pack2(d0, d1);
}

// Weight swizzle (same as R7/R13): element (r,c) at float index
//   r*128 + (((c>>2) ^ (r&31)) << 2) + (c&3)

// FORWARD: acc[ss] (f0), acc[4+ss] (f0+1); ss pairs: qA, qA+1, qA+16, qA+17.
// ws pre-offset by (fg&1)*2; cc = fg>>1.
__device__ __forceinline__ void accum_fwd(const float* __restrict__ ws, int cc,
                                          const u64 (*__restrict__ cur)[CPAD],
                                          int qA, u64 acc[8]) {
#pragma unroll 4
    for (int k = 0; k < HDIM; k++) {
        const float2 w = *reinterpret_cast<const float2*>(
            ws + k * 128 + (((k & 31) ^ cc) << 2));
        ull2 hA = *reinterpret_cast<const ull2*>(&cur[k][qA]);
        ull2 hB = *reinterpret_cast<const ull2*>(&cur[k][qA + 16]);
        u64 wa = pack2(w.x, w.x), wb = pack2(w.y, w.y);
        acc[0] = ffma2(hA.x, wa, acc[0]);  acc[1] = ffma2(hA.y, wa, acc[1]);
        acc[2] = ffma2(hB.x, wa, acc[2]);  acc[3] = ffma2(hB.y, wa, acc[3]);
        acc[4] = ffma2(hA.x, wb, acc[4]);  acc[5] = ffma2(hA.y, wb, acc[5]);
        acc[6] = ffma2(hB.x, wb, acc[6]);  acc[7] = ffma2(hB.y, wb, acc[7]);
    }
}

// BACKWARD: acc[ss] = dz_in for f0, acc[4+ss] for f0+1.
__device__ __forceinline__ void accum_bwd(const float* __restrict__ ws, int f0,
                                          const u64 (*__restrict__ cur)[CPAD],
                                          int qA, u64 acc[8]) {
    const float* r0b = ws + (f0 + 0) * 128;  const int x0m = (f0 + 0) & 31;
    const float* r1b = ws + (f0 + 1) * 128;  const int x1m = (f0 + 1) & 31;
#pragma unroll 4
    for (int k = 0; k < HDIM; k += 4) {
        int cc = k >> 2;
        float4 w0 = *reinterpret_cast<const float4*>(r0b + ((cc ^ x0m) << 2));
        float4 w1 = *reinterpret_cast<const float4*>(r1b + ((cc ^ x1m) << 2));
        ull2 hA0 = *reinterpret_cast<const ull2*>(&cur[k + 0][qA]);
        ull2 hA1 = *reinterpret_cast<const ull2*>(&cur[k + 1][qA]);
        ull2 hA2 = *reinterpret_cast<const ull2*>(&cur[k + 2][qA]);
        ull2 hA3 = *reinterpret_cast<const ull2*>(&cur[k + 3][qA]);
        ull2 hB0 = *reinterpret_cast<const ull2*>(&cur[k + 0][qA + 16]);
        ull2 hB1 = *reinterpret_cast<const ull2*>(&cur[k + 1][qA + 16]);
        ull2 hB2 = *reinterpret_cast<const ull2*>(&cur[k + 2][qA + 16]);
        ull2 hB3 = *reinterpret_cast<const ull2*>(&cur[k + 3][qA + 16]);

        u64 t;
        t = pack2(w0.x, w0.x);
        acc[0] = ffma2(hA0.x, t, acc[0]);  acc[1] = ffma2(hA0.y, t, acc[1]);
        acc[2] = ffma2(hB0.x, t, acc[2]);  acc[3] = ffma2(hB0.y, t, acc[3]);
        t = pack2(w0.y, w0.y);
        acc[0] = ffma2(hA1.x, t, acc[0]);  acc[1] = ffma2(hA1.y, t, acc[1]);
        acc[2] = ffma2(hB1.x, t, acc[2]);  acc[3] = ffma2(hB1.y, t, acc[3]);
        t = pack2(w0.z, w0.z);
        acc[0] = ffma2(hA2.x, t, acc[0]);  acc[1] = ffma2(hA2.y, t, acc[1]);
        acc[2] = ffma2(hB2.x, t, acc[2]);  acc[3] = ffma2(hB2.y, t, acc[3]);
        t = pack2(w0.w, w0.w);
        acc[0] = ffma2(hA3.x, t, acc[0]);  acc[1] = ffma2(hA3.y, t, acc[1]);
        acc[2] = ffma2(hB3.x, t, acc[2]);  acc[3] = ffma2(hB3.y, t, acc[3]);

        t = pack2(w1.x, w1.x);
        acc[4] = ffma2(hA0.x, t, acc[4]);  acc[5] = ffma2(hA0.y, t, acc[5]);
        acc[6] = ffma2(hB0.x, t, acc[6]);  acc[7] = ffma2(hB0.y, t, acc[7]);
        t = pack2(w1.y, w1.y);
        acc[4] = ffma2(hA1.x, t, acc[4]);  acc[5] = ffma2(hA1.y, t, acc[5]);
        acc[6] = ffma2(hB1.x, t, acc[6]);  acc[7] = ffma2(hB1.y, t, acc[7]);
        t = pack2(w1.z, w1.z);
        acc[4] = ffma2(hA2.x, t, acc[4]);  acc[5] = ffma2(hA2.y, t, acc[5]);
        acc[6] = ffma2(hB2.x, t, acc[6]);  acc[7] = ffma2(hB2.y, t, acc[7]);
        t = pack2(w1.w, w1.w);
        acc[4] = ffma2(hA3.x, t, acc[4]);  acc[5] = ffma2(hA3.y, t, acc[5]);
        acc[6] = ffma2(hB3.x, t, acc[6]);  acc[7] = ffma2(hB3.y, t, acc[7]);
    }
}

// SMEM layout (bytes):
//   cur 0 (32768) | w2s 32768 | w3s 98304 | w4s 163840 | w1s 229376 (1024)
//   b2s 230400 | b3s 230912 | b4s 231424 | xs 231936 (512)
#define SMEM_BYTES 232448

__global__ void __launch_bounds__(NTHR, 1)
ebm_mcmc_kernel(const float* __restrict__ x0,
                const float* __restrict__ w1, const float* __restrict__ b1,
                const float* __restrict__ w2, const float* __restrict__ b2,
                const float* __restrict__ w3, const float* __restrict__ b3,
                const float* __restrict__ w4, const float* __restrict__ b4,
                const float* __restrict__ w5,
                const float* __restrict__ noise,
                float* __restrict__ out, int nsamp) {
    extern __shared__ unsigned char smraw[];
    u64 (*cur)[CPAD] = reinterpret_cast<u64(*)[CPAD]>(smraw);
    float* w2s = reinterpret_cast<float*>(smraw + 32768);
    float* w3s = w2s + HDIM * 128;
    float* w4s = w3s + HDIM * 128;
    float* w1s = w4s + HDIM * 128;    // [2][128]
    float* b2s = w1s + 256;
    float* b3s = b2s + 128;
    float* b4s = b3s + 128;
    u64*   xs  = reinterpret_cast<u64*>(b4s + 128);   // xs[d*32 + pair]

    const int tid = threadIdx.x;
    const int fg  = tid >> 3;         // 0..63
    const int f0  = fg << 1;          // 2 contiguous output features
    const int cc0 = fg >> 1;          // 16B chunk holding f0
    const int qA  = (tid & 7) * 2;    // pairs qA,qA+1 and qA+16,qA+17
    const int s0  = blockIdx.x * SB;

    // ---- load weights into SMEM (swizzled), once per block ----
    for (int idx = tid; idx < HDIM * HDIM; idx += NTHR) {
        int r = idx >> 7, c = idx & 127;
        int o = r * 128 + ((((c >> 2) ^ (r & 31)) << 2) | (c & 3));
        w2s[o] = w2[idx];
        w3s[o] = w3[idx];
        w4s[o] = w4[idx];
    }
    if (tid < 256) w1s[tid] = w1[tid];
    if (tid < 128) {
        b2s[tid] = b2[tid];
        b3s[tid] = b3[tid];
        b4s[tid] = b4[tid];
    }
    if (tid < 64) {
        int d = tid >> 5, p = tid & 31;
        size_t bx = (size_t)(s0 + 2 * p) * 2 + d;
        xs[tid] = pack2(x0[bx], x0[bx + 2]);
    }
    // per-thread constants in registers
    const float w1a0 = w1[f0],       w1a1 = w1[f0 + 1];
    const float w1b0 = w1[128 + f0], w1b1 = w1[128 + f0 + 1];
    const float b1c0 = b1[f0], b1c1 = b1[f0 + 1];
    const float w5c0 = w5[f0], w5c1 = w5[f0 + 1];
    __syncthreads();

    // silu' for layers 2,3 (8 each = 2f x 4 pairs); sd1 recomputed; sd4 transient
    u64 sd2[8], sd3[8];

    // weight pointer pre-offset for the fwd float2 load
    const float* w2f = w2s + ((fg & 1) << 1);
    const float* w3f = w3s + ((fg & 1) << 1);
    const float* w4f = w4s + ((fg & 1) << 1);

    // update-phase mapping (8 j-partitions of 16)
    const int jp = tid & 7;
    const int ug = tid >> 3;       // 0..63
    const int ud = ug >> 5;        // dim
    const int uq = ug & 31;        // pair

    for (int i = 0; i < NSTEPS; i++) {
        float eps = 10.0f * (1.0f - (float)i / 60.0f);
        float cn  = sqrtf(2.0f * eps) * 0.005f;

        float nz0 = 0.0f, nz1 = 0.0f;
        if (jp == 0) {
            size_t base = ((size_t)i * nsamp + s0 + 2 * uq) * 2 + ud;
            nz0 = noise[base];
            nz1 = noise[base + 2];
        }

        // ---- forward L1 ----
        {
            u64 wa0 = pack2(w1a0, w1a0), wa1 = pack2(w1a1, w1a1);
            u64 wb0 = pack2(w1b0, w1b0), wb1 = pack2(w1b1, w1b1);
            u64 bb0 = pack2(b1c0, b1c0), bb1 = pack2(b1c1, b1c1);
            u64 xA0 = xs[qA],      xA1 = xs[qA + 1];
            u64 xB0 = xs[qA + 16], xB1 = xs[qA + 17];
            u64 yA0 = xs[32 + qA],      yA1 = xs[32 + qA + 1];
            u64 yB0 = xs[32 + qA + 16], yB1 = xs[32 + qA + 17];
            u64 h[8], du;
            silu2(ffma2(xA0, wa0, ffma2(yA0, wb0, bb0)), h[0], du);
            silu2(ffma2(xA1, wa0, ffma2(yA1, wb0, bb0)), h[1], du);
            silu2(ffma2(xB0, wa0, ffma2(yB0, wb0, bb0)), h[2], du);
            silu2(ffma2(xB1, wa0, ffma2(yB1, wb0, bb0)), h[3], du);
            silu2(ffma2(xA0, wa1, ffma2(yA0, wb1, bb1)), h[4], du);
            silu2(ffma2(xA1, wa1, ffma2(yA1, wb1, bb1)), h[5], du);
            silu2(ffma2(xB0, wa1, ffma2(yB0, wb1, bb1)), h[6], du);
            silu2(ffma2(xB1, wa1, ffma2(yB1, wb1, bb1)), h[7], du);
            ull2 sa; sa.x = h[0]; sa.y = h[1];
            ull2 sb; sb.x = h[2]; sb.y = h[3];
            *reinterpret_cast<ull2*>(&cur[f0][qA])      = sa;
            *reinterpret_cast<ull2*>(&cur[f0][qA + 16]) = sb;
            ull2 sc; sc.x = h[4]; sc.y = h[5];
            ull2 sd; sd.x = h[6]; sd.y = h[7];
            *reinterpret_cast<ull2*>(&cur[f0 + 1][qA])      = sc;
            *reinterpret_cast<ull2*>(&cur[f0 + 1][qA + 16]) = sd;
        }
        __syncthreads();

        // ---- forward L2 ----
        {
            u64 acc[8];
            float bv0 = b2s[f0], bv1 = b2s[f0 + 1];
            u64 bp0 = pack2(bv0, bv0), bp1 = pack2(bv1, bv1);
            acc[0] = acc[1] = acc[2] = acc[3] = bp0;
            acc[4] = acc[5] = acc[6] = acc[7] = bp1;
            accum_fwd(w2f, cc0, cur, qA, acc);
            __syncthreads();
            u64 h[8];
#pragma unroll
            for (int q = 0; q < 8; q++) silu2(acc[q], h[q], sd2[q]);
            ull2 sa; sa.x = h[0]; sa.y = h[1];
            ull2 sb; sb.x = h[2]; sb.y = h[3];
            *reinterpret_cast<ull2*>(&cur[f0][qA])      = sa;
            *reinterpret_cast<ull2*>(&cur[f0][qA + 16]) = sb;
            ull2 sc; sc.x = h[4]; sc.y = h[5];
            ull2 sd; sd.x = h[6]; sd.y = h[7];
            *reinterpret_cast<ull2*>(&cur[f0 + 1][qA])      = sc;
            *reinterpret_cast<ull2*>(&cur[f0 + 1][qA + 16]) = sd;
        }
        __syncthreads();

        // ---- forward L3 ----
        {
            u64 acc[8];
            float bv0 = b3s[f0], bv1 = b3s[f0 + 1];
            u64 bp0 = pack2(bv0, bv0), bp1 = pack2(bv1, bv1);
            acc[0] = acc[1] = acc[2] = acc[3] = bp0;
            acc[4] = acc[5] = acc[6] = acc[7] = bp1;
            accum_fwd(w3f, cc0, cur, qA, acc);
            __syncthreads();
            u64 h[8];
#pragma unroll
            for (int q = 0; q < 8; q++) silu2(acc[q], h[q], sd3[q]);
            ull2 sa; sa.x = h[0]; sa.y = h[1];
            ull2 sb; sb.x = h[2]; sb.y = h[3];
            *reinterpret_cast<ull2*>(&cur[f0][qA])      = sa;
            *reinterpret_cast<ull2*>(&cur[f0][qA + 16]) = sb;
            ull2 sc; sc.x = h[4]; sc.y = h[5];
            ull2 sd; sd.x = h[6]; sd.y = h[7];
            *reinterpret_cast<ull2*>(&cur[f0 + 1][qA])      = sc;
            *reinterpret_cast<ull2*>(&cur[f0 + 1][qA + 16]) = sd;
        }
        __syncthreads();

        // ---- forward L4 (h4 dead) + seed dz4 = w5 .* silu'(z4) ----
        {
            u64 acc[8];
            float bv0 = b4s[f0], bv1 = b4s[f0 + 1];
            u64 bp0 = pack2(bv0, bv0), bp1 = pack2(bv1, bv1);
            acc[0] = acc[1] = acc[2] = acc[3] = bp0;
            acc[4] = acc[5] = acc[6] = acc[7] = bp1;
            accum_fwd(w4f, cc0, cur, qA, acc);
            u64 wp0 = pack2(w5c0, w5c0), wp1 = pack2(w5c1, w5c1);
            u64 dz[8];
#pragma unroll
            for (int q = 0; q < 8; q++) {
                u64 h, d;
                silu2(acc[q], h, d);
                dz[q] = fmul2((q < 4) ? wp0 : wp1, d);
            }
            __syncthreads();   // all reads of h3 done
            ull2 sa; sa.x = dz[0]; sa.y = dz[1];
            ull2 sb; sb.x = dz[2]; sb.y = dz[3];
            *reinterpret_cast<ull2*>(&cur[f0][qA])      = sa;
            *reinterpret_cast<ull2*>(&cur[f0][qA + 16]) = sb;
            ull2 sc; sc.x = dz[4]; sc.y = dz[5];
            ull2 sd; sd.x = dz[6]; sd.y = dz[7];
            *reinterpret_cast<ull2*>(&cur[f0 + 1][qA])      = sc;
            *reinterpret_cast<ull2*>(&cur[f0 + 1][qA + 16]) = sd;
        }
        __syncthreads();

        // ---- backward W4 -> dz3 ----
        {
            u64 acc[8];
#pragma unroll
            for (int q = 0; q < 8; q++) acc[q] = 0ULL;
            accum_bwd(w4s, f0, cur, qA, acc);
            __syncthreads();
            u64 dz[8];
#pragma unroll
            for (int q = 0; q < 8; q++) dz[q] = fmul2(acc[q], sd3[q]);
            ull2 sa; sa.x = dz[0]; sa.y = dz[1];
            ull2 sb; sb.x = dz[2]; sb.y = dz[3];
            *reinterpret_cast<ull2*>(&cur[f0][qA])      = sa;
            *reinterpret_cast<ull2*>(&cur[f0][qA + 16]) = sb;
            ull2 sc; sc.x = dz[4]; sc.y = dz[5];
            ull2 sd; sd.x = dz[6]; sd.y = dz[7];
            *reinterpret_cast<ull2*>(&cur[f0 + 1][qA])      = sc;
            *reinterpret_cast<ull2*>(&cur[f0 + 1][qA + 16]) = sd;
        }
        __syncthreads();

        // ---- backward W3 -> dz2 ----
        {
            u64 acc[8];
#pragma unroll
            for (int q = 0; q < 8; q++) acc[q] = 0ULL;
            accum_bwd(w3s, f0, cur, qA, acc);
            __syncthreads();
            u64 dz[8];
#pragma unroll
            for (int q = 0; q < 8; q++) dz[q] = fmul2(acc[q], sd2[q]);
            ull2 sa; sa.x = dz[0]; sa.y = dz[1];
            ull2 sb; sb.x = dz[2]; sb.y = dz[3];
            *reinterpret_cast<ull2*>(&cur[f0][qA])      = sa;
            *reinterpret_cast<ull2*>(&cur[f0][qA + 16]) = sb;
            ull2 sc; sc.x = dz[4]; sc.y = dz[5];
            ull2 sd; sd.x = dz[6]; sd.y = dz[7];
            *reinterpret_cast<ull2*>(&cur[f0 + 1][qA])      = sc;
            *reinterpret_cast<ull2*>(&cur[f0 + 1][qA + 16]) = sd;
        }
        __syncthreads();

        // ---- backward W2 -> dz1 (sd1 recomputed) ----
        {
            u64 acc[8];
#pragma unroll
            for (int q = 0; q < 8; q++) acc[q] = 0ULL;
            accum_bwd(w2s, f0, cur, qA, acc);
            u64 wa0 = pack2(w1a0, w1a0), wa1 = pack2(w1a1, w1a1);
            u64 wb0 = pack2(w1b0, w1b0), wb1 = pack2(w1b1, w1b1);
            u64 bb0 = pack2(b1c0, b1c0), bb1 = pack2(b1c1, b1c1);
            u64 xA0 = xs[qA],      xA1 = xs[qA + 1];
            u64 xB0 = xs[qA + 16], xB1 = xs[qA + 17];
            u64 yA0 = xs[32 + qA],      yA1 = xs[32 + qA + 1];
            u64 yB0 = xs[32 + qA + 16], yB1 = xs[32 + qA + 17];
            u64 dz[8];
            {
                u64 h, d;
                silu2(ffma2(xA0, wa0, ffma2(yA0, wb0, bb0)), h, d);
                dz[0] = fmul2(acc[0], d);
                silu2(ffma2(xA1, wa0, ffma2(yA1, wb0, bb0)), h, d);
                dz[1] = fmul2(acc[1], d);
                silu2(ffma2(xB0, wa0, ffma2(yB0, wb0, bb0)), h, d);
                dz[2] = fmul2(acc[2], d);
                silu2(ffma2(xB1, wa0, ffma2(yB1, wb0, bb0)), h, d);
                dz[3] = fmul2(acc[3], d);
                silu2(ffma2(xA0, wa1, ffma2(yA0, wb1, bb1)), h, d);
                dz[4] = fmul2(acc[4], d);
                silu2(ffma2(xA1, wa1, ffma2(yA1, wb1, bb1)), h, d);
                dz[5] = fmul2(acc[5], d);
                silu2(ffma2(xB0, wa1, ffma2(yB0, wb1, bb1)), h, d);
                dz[6] = fmul2(acc[6], d);
                silu2(ffma2(xB1, wa1, ffma2(yB1, wb1, bb1)), h, d);
                dz[7] = fmul2(acc[7], d);
            }
            __syncthreads();
            ull2 sa; sa.x = dz[0]; sa.y = dz[1];
            ull2 sb; sb.x = dz[2]; sb.y = dz[3];
            *reinterpret_cast<ull2*>(&cur[f0][qA])      = sa;
            *reinterpret_cast<ull2*>(&cur[f0][qA + 16]) = sb;
            ull2 sc; sc.x = dz[4]; sc.y = dz[5];
            ull2 sd; sd.x = dz[6]; sd.y = dz[7];
            *reinterpret_cast<ull2*>(&cur[f0 + 1][qA])      = sc;
            *reinterpret_cast<ull2*>(&cur[f0 + 1][qA + 16]) = sd;
        }
        __syncthreads();

        // ---- g = dz1 @ W1^T, clip, Langevin update ----
        {
            u64 g = 0ULL;
#pragma unroll
            for (int jj = 0; jj < 16; jj++) {
                int j = jp * 16 + jj;
                float w = w1s[ud * 128 + j];
                g = ffma2(cur[j][uq], pack2(w, w), g);
            }
            g = fadd2(g, __shfl_down_sync(0xffffffffu, g, 4, 8));
            g = fadd2(g, __shfl_down_sync(0xffffffffu, g, 2, 8));
            g = fadd2(g, __shfl_down_sync(0xffffffffu, g, 1, 8));
            if (jp == 0) {
                float2 gv = unpack2(g);
                gv.x = fminf(fmaxf(gv.x, -0.03f), 0.03f);
                gv.y = fminf(fmaxf(gv.y, -0.03f), 0.03f);
                float2 xv = unpack2(xs[ud * 32 + uq]);
                float ax = xv.x + cn * nz0;  ax += eps * gv.x;
                float ay = xv.y + cn * nz1;  ay += eps * gv.y;
                ax = fminf(fmaxf(ax, -2.43f), 3.05f);
                ay = fminf(fmaxf(ay, -2.43f), 3.05f);
                xs[ud * 32 + uq] = pack2(ax, ay);
            }
        }
        __syncthreads();
    }

    // ---- write final x ----
    if (tid < 128) {
        int s = tid >> 1, d = tid & 1;
        float2 v = unpack2(xs[d * 32 + (s >> 1)]);
        out[(size_t)(s0 + s) * 2 + d] = (s & 1) ? v.y : v.x;
    }
}

extern "C" void kernel_launch(void* const* d_in, const int* in_sizes, int n_in,
                              void* d_out, int out_size) {
    const float* x0    = (const float*)d_in[0];
    const float* w1    = (const float*)d_in[1];
    const float* b1    = (const float*)d_in[2];
    const float* w2    = (const float*)d_in[3];
    const float* b2    = (const float*)d_in[4];
    const float* w3    = (const float*)d_in[5];
    const float* b3    = (const float*)d_in[6];
    const float* w4    = (const float*)d_in[7];
    const float* b4    = (const float*)d_in[8];
    const float* w5    = (const float*)d_in[9];
    const float* noise = (const float*)d_in[11];
    float* out = (float*)d_out;

    int nsamp = in_sizes[0] / 2;
    cudaFuncSetAttribute(ebm_mcmc_kernel,
                         cudaFuncAttributeMaxDynamicSharedMemorySize, SMEM_BYTES);
    int nblocks = nsamp / SB;
    ebm_mcmc_kernel<<<nblocks, NTHR, SMEM_BYTES>>>(
        x0, w1, b1, w2, b2, w3, b3, w4, b4, w5, noise, out, nsamp);
}

// round 15
// speedup vs baseline: 1.3479x; 1.3479x over previous
#include <cuda_runtime.h>

#define HDIM   128
#define NSTEPS 60
#define SB     64      // samples per block
#define NTHR   256
#define CPAD   32      // cur row length in u64 pairs

typedef unsigned long long u64;
typedef ulonglong2 ull2;

__device__ __forceinline__ u64 pack2(float a, float b) {
    u64 r; asm("mov.b64 %0, {%1, %2};" : "=l"(r) : "f"(a), "f"(b)); return r;
}
__device__ __forceinline__ float2 unpack2(u64 v) {
    float2 r; asm("mov.b64 {%0, %1}, %2;" : "=f"(r.x), "=f"(r.y) : "l"(v)); return r;
}
__device__ __forceinline__ u64 ffma2(u64 a, u64 b, u64 c) {
    u64 d; asm("fma.rn.f32x2 %0, %1, %2, %3;" : "=l"(d) : "l"(a), "l"(b), "l"(c)); return d;
}
__device__ __forceinline__ u64 fmul2(u64 a, u64 b) {
    u64 d; asm("mul.rn.f32x2 %0, %1, %2;" : "=l"(d) : "l"(a), "l"(b)); return d;
}
__device__ __forceinline__ u64 fadd2(u64 a, u64 b) {
    u64 d; asm("add.rn.f32x2 %0, %1, %2;" : "=l"(d) : "l"(a), "l"(b)); return d;
}
__device__ __forceinline__ void silu2(u64 z, u64& h, u64& d) {
    float2 zf = unpack2(z);
    float e0 = __expf(-zf.x), e1 = __expf(-zf.y);
    float s0 = 1.0f / (1.0f + e0), s1 = 1.0f / (1.0f + e1);
    float h0 = zf.x * s0,          h1 = zf.y * s1;
    float d0 = fmaf(h0, 1.0f - s0, s0);
    float d1 = fmaf(h1, 1.0f - s1, s1);
    h = pack2(h0, h1);
    d = pack2(d0, d1);
}

// FORWARD: acc[ff*4+ss] += sum_k W[k][f0+ff] * cur[k][pair]
// Weights from GLOBAL (L2-resident, shared by all blocks); row-major W[k*128+f].
__device__ __forceinline__ void accum_fwd(const float* __restrict__ wg, int f0,
                                          const u64 (*__restrict__ cur)[CPAD],
                                          int qA, u64 acc[16]) {
#pragma unroll 4
    for (int k = 0; k < HDIM; k++) {
        const float4 w = __ldg(reinterpret_cast<const float4*>(wg + k * 128 + f0));
        ull2 hA = *reinterpret_cast<const ull2*>(&cur[k][qA]);
        ull2 hB = *reinterpret_cast<const ull2*>(&cur[k][qA + 16]);
        u64 wa = pack2(w.x, w.x), wb = pack2(w.y, w.y);
        u64 wc = pack2(w.z, w.z), wd = pack2(w.w, w.w);
        acc[0]  = ffma2(hA.x, wa, acc[0]);   acc[1]  = ffma2(hA.y, wa, acc[1]);
        acc[2]  = ffma2(hB.x, wa, acc[2]);   acc[3]  = ffma2(hB.y, wa, acc[3]);
        acc[4]  = ffma2(hA.x, wb, acc[4]);   acc[5]  = ffma2(hA.y, wb, acc[5]);
        acc[6]  = ffma2(hB.x, wb, acc[6]);   acc[7]  = ffma2(hB.y, wb, acc[7]);
        acc[8]  = ffma2(hA.x, wc, acc[8]);   acc[9]  = ffma2(hA.y, wc, acc[9]);
        acc[10] = ffma2(hB.x, wc, acc[10]);  acc[11] = ffma2(hB.y, wc, acc[11]);
        acc[12] = ffma2(hA.x, wd, acc[12]);  acc[13] = ffma2(hA.y, wd, acc[13]);
        acc[14] = ffma2(hB.x, wd, acc[14]);  acc[15] = ffma2(hB.y, wd, acc[15]);
    }
}

// BACKWARD: acc[ff*4+ss] += sum_k W[f0+ff][k] * cur[k][pair]  (rows from global)
__device__ __forceinline__ void accum_bwd(const float* __restrict__ wg, int f0,
                                          const u64 (*__restrict__ cur)[CPAD],
                                          int qA, u64 acc[16]) {
    const float* r0b = wg + (f0 + 0) * 128;
    const float* r1b = wg + (f0 + 1) * 128;
    const float* r2b = wg + (f0 + 2) * 128;
    const float* r3b = wg + (f0 + 3) * 128;
#pragma unroll 4
    for (int k = 0; k < HDIM; k += 4) {
        float4 w0 = __ldg(reinterpret_cast<const float4*>(r0b + k));
        float4 w1 = __ldg(reinterpret_cast<const float4*>(r1b + k));
        float4 w2 = __ldg(reinterpret_cast<const float4*>(r2b + k));
        float4 w3 = __ldg(reinterpret_cast<const float4*>(r3b + k));
        ull2 hA0 = *reinterpret_cast<const ull2*>(&cur[k + 0][qA]);
        ull2 hA1 = *reinterpret_cast<const ull2*>(&cur[k + 1][qA]);
        ull2 hA2 = *reinterpret_cast<const ull2*>(&cur[k + 2][qA]);
        ull2 hA3 = *reinterpret_cast<const ull2*>(&cur[k + 3][qA]);
        ull2 hB0 = *reinterpret_cast<const ull2*>(&cur[k + 0][qA + 16]);
        ull2 hB1 = *reinterpret_cast<const ull2*>(&cur[k + 1][qA + 16]);
        ull2 hB2 = *reinterpret_cast<const ull2*>(&cur[k + 2][qA + 16]);
        ull2 hB3 = *reinterpret_cast<const ull2*>(&cur[k + 3][qA + 16]);

        u64 t;
        t = pack2(w0.x, w0.x);
        acc[0] = ffma2(hA0.x, t, acc[0]);  acc[1] = ffma2(hA0.y, t, acc[1]);
        acc[2] = ffma2(hB0.x, t, acc[2]);  acc[3] = ffma2(hB0.y, t, acc[3]);
        t = pack2(w0.y, w0.y);
        acc[0] = ffma2(hA1.x, t, acc[0]);  acc[1] = ffma2(hA1.y, t, acc[1]);
        acc[2] = ffma2(hB1.x, t, acc[2]);  acc[3] = ffma2(hB1.y, t, acc[3]);
        t = pack2(w0.z, w0.z);
        acc[0] = ffma2(hA2.x, t, acc[0]);  acc[1] = ffma2(hA2.y, t, acc[1]);
        acc[2] = ffma2(hB2.x, t, acc[2]);  acc[3] = ffma2(hB2.y, t, acc[3]);
        t = pack2(w0.w, w0.w);
        acc[0] = ffma2(hA3.x, t, acc[0]);  acc[1] = ffma2(hA3.y, t, acc[1]);
        acc[2] = ffma2(hB3.x, t, acc[2]);  acc[3] = ffma2(hB3.y, t, acc[3]);

        t = pack2(w1.x, w1.x);
        acc[4] = ffma2(hA0.x, t, acc[4]);  acc[5] = ffma2(hA0.y, t, acc[5]);
        acc[6] = ffma2(hB0.x, t, acc[6]);  acc[7] = ffma2(hB0.y, t, acc[7]);
        t = pack2(w1.y, w1.y);
        acc[4] = ffma2(hA1.x, t, acc[4]);  acc[5] = ffma2(hA1.y, t, acc[5]);
        acc[6] = ffma2(hB1.x, t, acc[6]);  acc[7] = ffma2(hB1.y, t, acc[7]);
        t = pack2(w1.z, w1.z);
        acc[4] = ffma2(hA2.x, t, acc[4]);  acc[5] = ffma2(hA2.y, t, acc[5]);
        acc[6] = ffma2(hB2.x, t, acc[6]);  acc[7] = ffma2(hB2.y, t, acc[7]);
        t = pack2(w1.w, w1.w);
        acc[4] = ffma2(hA3.x, t, acc[4]);  acc[5] = ffma2(hA3.y, t, acc[5]);
        acc[6] = ffma2(hB3.x, t, acc[6]);  acc[7] = ffma2(hB3.y, t, acc[7]);

        t = pack2(w2.x, w2.x);
        acc[8]  = ffma2(hA0.x, t, acc[8]);   acc[9]  = ffma2(hA0.y, t, acc[9]);
        acc[10] = ffma2(hB0.x, t, acc[10]);  acc[11] = ffma2(hB0.y, t, acc[11]);
        t = pack2(w2.y, w2.y);
        acc[8]  = ffma2(hA1.x, t, acc[8]);   acc[9]  = ffma2(hA1.y, t, acc[9]);
        acc[10] = ffma2(hB1.x, t, acc[10]);  acc[11] = ffma2(hB1.y, t, acc[11]);
        t = pack2(w2.z, w2.z);
        acc[8]  = ffma2(hA2.x, t, acc[8]);   acc[9]  = ffma2(hA2.y, t, acc[9]);
        acc[10] = ffma2(hB2.x, t, acc[10]);  acc[11] = ffma2(hB2.y, t, acc[11]);
        t = pack2(w2.w, w2.w);
        acc[8]  = ffma2(hA3.x, t, acc[8]);   acc[9]  = ffma2(hA3.y, t, acc[9]);
        acc[10] = ffma2(hB3.x, t, acc[10]);  acc[11] = ffma2(hB3.y, t, acc[11]);

        t = pack2(w3.x, w3.x);
        acc[12] = ffma2(hA0.x, t, acc[12]);  acc[13] = ffma2(hA0.y, t, acc[13]);
        acc[14] = ffma2(hB0.x, t, acc[14]);  acc[15] = ffma2(hB0.y, t, acc[15]);
        t = pack2(w3.y, w3.y);
        acc[12] = ffma2(hA1.x, t, acc[12]);  acc[13] = ffma2(hA1.y, t, acc[13]);
        acc[14] = ffma2(hB1.x, t, acc[14]);  acc[15] = ffma2(hB1.y, t, acc[15]);
        t = pack2(w3.z, w3.z);
        acc[12] = ffma2(hA2.x, t, acc[12]);  acc[13] = ffma2(hA2.y, t, acc[13]);
        acc[14] = ffma2(hB2.x, t, acc[14]);  acc[15] = ffma2(hB2.y, t, acc[15]);
        t = pack2(w3.w, w3.w);
        acc[12] = ffma2(hA3.x, t, acc[12]);  acc[13] = ffma2(hA3.y, t, acc[13]);
        acc[14] = ffma2(hB3.x, t, acc[14]);  acc[15] = ffma2(hB3.y, t, acc[15]);
    }
}

// SMEM (bytes): cur 0 (32768) | w1s 32768 (1024) | b1s 33792 | b2s 34304
//               b3s 34816 | b4s 35328 | w5s 35840 | xs 36352 (512) -> 36864 total
#define SMEM_BYTES 36864

__global__ void __launch_bounds__(NTHR, 2)
ebm_mcmc_kernel(const float* __restrict__ x0,
                const float* __restrict__ w1, const float* __restrict__ b1,
                const float* __restrict__ w2, const float* __restrict__ b2,
                const float* __restrict__ w3, const float* __restrict__ b3,
                const float* __restrict__ w4, const float* __restrict__ b4,
                const float* __restrict__ w5,
                const float* __restrict__ noise,
                float* __restrict__ out, int nsamp) {
    extern __shared__ unsigned char smraw[];
    u64 (*cur)[CPAD] = reinterpret_cast<u64(*)[CPAD]>(smraw);
    float* w1s = reinterpret_cast<float*>(smraw + 32768);  // [2][128]
    float* b1s = w1s + 256;
    float* b2s = b1s + 128;
    float* b3s = b2s + 128;
    float* b4s = b3s + 128;
    float* w5s = b4s + 128;
    u64*   xs  = reinterpret_cast<u64*>(w5s + 128);        // xs[d*32 + pair]

    const int tid = threadIdx.x;
    const int f0  = (tid >> 3) * 4;   // 4 contiguous output features
    const int qA  = (tid & 7) * 2;    // pairs qA,qA+1 and qA+16,qA+17
    const int s0  = blockIdx.x * SB;

    if (tid < 256) w1s[tid] = w1[tid];
    if (tid < 128) {
        b1s[tid] = b1[tid];
        b2s[tid] = b2[tid];
        b3s[tid] = b3[tid];
        b4s[tid] = b4[tid];
        w5s[tid] = w5[tid];
    }
    if (tid < 64) {
        int d = tid >> 5, p = tid & 31;
        size_t bx = (size_t)(s0 + 2 * p) * 2 + d;
        xs[tid] = pack2(x0[bx], x0[bx + 2]);
    }
    __syncthreads();

    // silu' for layers 2,3 (16 each = 4f x 4 pairs); sd1 recomputed; sd4 transient
    u64 sd2[16], sd3[16];

    // update-phase mapping: jp width 4 (32 j each)
    const int jp = tid & 3;
    const int ug = tid >> 2;       // 0..63
    const int ud = ug >> 5;        // dim
    const int uq = ug & 31;        // pair

    for (int i = 0; i < NSTEPS; i++) {
        float eps = 10.0f * (1.0f - (float)i / 60.0f);
        float cn  = sqrtf(2.0f * eps) * 0.005f;

        float nz0 = 0.0f, nz1 = 0.0f;
        if (jp == 0) {
            size_t base = ((size_t)i * nsamp + s0 + 2 * uq) * 2 + ud;
            nz0 = noise[base];
            nz1 = noise[base + 2];
        }

        // ---- forward L1 ----
        {
            float4 wa = *reinterpret_cast<const float4*>(w1s + f0);
            float4 wb = *reinterpret_cast<const float4*>(w1s + 128 + f0);
            float4 bbq = *reinterpret_cast<const float4*>(b1s + f0);
            u64 xA0 = xs[qA],      xA1 = xs[qA + 1];
            u64 xB0 = xs[qA + 16], xB1 = xs[qA + 17];
            u64 yA0 = xs[32 + qA],      yA1 = xs[32 + qA + 1];
            u64 yB0 = xs[32 + qA + 16], yB1 = xs[32 + qA + 17];
            float wav[4] = {wa.x, wa.y, wa.z, wa.w};
            float wbv[4] = {wb.x, wb.y, wb.z, wb.w};
            float bbv[4] = {bbq.x, bbq.y, bbq.z, bbq.w};
#pragma unroll
            for (int ff = 0; ff < 4; ff++) {
                u64 wap = pack2(wav[ff], wav[ff]);
                u64 wbp = pack2(wbv[ff], wbv[ff]);
                u64 bbp = pack2(bbv[ff], bbv[ff]);
                u64 zA0 = ffma2(xA0, wap, ffma2(yA0, wbp, bbp));
                u64 zA1 = ffma2(xA1, wap, ffma2(yA1, wbp, bbp));
                u64 zB0 = ffma2(xB0, wap, ffma2(yB0, wbp, bbp));
                u64 zB1 = ffma2(xB1, wap, ffma2(yB1, wbp, bbp));
                u64 hA0, hA1, hB0, hB1, du;
                silu2(zA0, hA0, du);  silu2(zA1, hA1, du);
                silu2(zB0, hB0, du);  silu2(zB1, hB1, du);
                ull2 sa; sa.x = hA0; sa.y = hA1;
                ull2 sb; sb.x = hB0; sb.y = hB1;
                *reinterpret_cast<ull2*>(&cur[f0 + ff][qA])      = sa;
                *reinterpret_cast<ull2*>(&cur[f0 + ff][qA + 16]) = sb;
            }
        }
        __syncthreads();

        // ---- forward L2 ----
        {
            u64 acc[16];
            float4 bb = *reinterpret_cast<const float4*>(b2s + f0);
            float bbv[4] = {bb.x, bb.y, bb.z, bb.w};
#pragma unroll
            for (int ff = 0; ff < 4; ff++) {
                u64 bp = pack2(bbv[ff], bbv[ff]);
                acc[4 * ff] = acc[4 * ff + 1] = acc[4 * ff + 2] = acc[4 * ff + 3] = bp;
            }
            accum_fwd(w2, f0, cur, qA, acc);
            __syncthreads();
#pragma unroll
            for (int ff = 0; ff < 4; ff++) {
                u64 hA0, hA1, hB0, hB1;
                silu2(acc[4 * ff],     hA0, sd2[4 * ff]);
                silu2(acc[4 * ff + 1], hA1, sd2[4 * ff + 1]);
                silu2(acc[4 * ff + 2], hB0, sd2[4 * ff + 2]);
                silu2(acc[4 * ff + 3], hB1, sd2[4 * ff + 3]);
                ull2 sa; sa.x = hA0; sa.y = hA1;
                ull2 sb; sb.x = hB0; sb.y = hB1;
                *reinterpret_cast<ull2*>(&cur[f0 + ff][qA])      = sa;
                *reinterpret_cast<ull2*>(&cur[f0 + ff][qA + 16]) = sb;
            }
        }
        __syncthreads();

        // ---- forward L3 ----
        {
            u64 acc[16];
            float4 bb = *reinterpret_cast<const float4*>(b3s + f0);
            float bbv[4] = {bb.x, bb.y, bb.z, bb.w};
#pragma unroll
            for (int ff = 0; ff < 4; ff++) {
                u64 bp = pack2(bbv[ff], bbv[ff]);
                acc[4 * ff] = acc[4 * ff + 1] = acc[4 * ff + 2] = acc[4 * ff + 3] = bp;
            }
            accum_fwd(w3, f0, cur, qA, acc);
            __syncthreads();
#pragma unroll
            for (int ff = 0; ff < 4; ff++) {
                u64 hA0, hA1, hB0, hB1;
                silu2(acc[4 * ff],     hA0, sd3[4 * ff]);
                silu2(acc[4 * ff + 1], hA1, sd3[4 * ff + 1]);
                silu2(acc[4 * ff + 2], hB0, sd3[4 * ff + 2]);
                silu2(acc[4 * ff + 3], hB1, sd3[4 * ff + 3]);
                ull2 sa; sa.x = hA0; sa.y = hA1;
                ull2 sb; sb.x = hB0; sb.y = hB1;
                *reinterpret_cast<ull2*>(&cur[f0 + ff][qA])      = sa;
                *reinterpret_cast<ull2*>(&cur[f0 + ff][qA + 16]) = sb;
            }
        }
        __syncthreads();

        // ---- forward L4 (h4 dead) + seed dz4 = w5 .* silu'(z4) ----
        {
            u64 acc[16];
            float4 bb = *reinterpret_cast<const float4*>(b4s + f0);
            float bbv[4] = {bb.x, bb.y, bb.z, bb.w};
#pragma unroll
            for (int ff = 0; ff < 4; ff++) {
                u64 bp = pack2(bbv[ff], bbv[ff]);
                acc[4 * ff] = acc[4 * ff + 1] = acc[4 * ff + 2] = acc[4 * ff + 3] = bp;
            }
            accum_fwd(w4, f0, cur, qA, acc);
            float4 w5q = *reinterpret_cast<const float4*>(w5s + f0);
            float w5a[4] = {w5q.x, w5q.y, w5q.z, w5q.w};
            u64 dz[16];
#pragma unroll
            for (int ff = 0; ff < 4; ff++) {
                u64 h, d0, d1, d2, d3;
                silu2(acc[4 * ff],     h, d0);
                silu2(acc[4 * ff + 1], h, d1);
                silu2(acc[4 * ff + 2], h, d2);
                silu2(acc[4 * ff + 3], h, d3);
                u64 wp = pack2(w5a[ff], w5a[ff]);
                dz[4 * ff]     = fmul2(wp, d0);
                dz[4 * ff + 1] = fmul2(wp, d1);
                dz[4 * ff + 2] = fmul2(wp, d2);
                dz[4 * ff + 3] = fmul2(wp, d3);
            }
            __syncthreads();   // all reads of h3 done
#pragma unroll
            for (int ff = 0; ff < 4; ff++) {
                ull2 sa; sa.x = dz[4 * ff];     sa.y = dz[4 * ff + 1];
                ull2 sb; sb.x = dz[4 * ff + 2]; sb.y = dz[4 * ff + 3];
                *reinterpret_cast<ull2*>(&cur[f0 + ff][qA])      = sa;
                *reinterpret_cast<ull2*>(&cur[f0 + ff][qA + 16]) = sb;
            }
        }
        __syncthreads();

        // ---- backward W4 -> dz3 ----
        {
            u64 acc[16];
#pragma unroll
            for (int q = 0; q < 16; q++) acc[q] = 0ULL;
            accum_bwd(w4, f0, cur, qA, acc);
            __syncthreads();
#pragma unroll
            for (int ff = 0; ff < 4; ff++) {
                ull2 sa, sb;
                sa.x = fmul2(acc[4 * ff],     sd3[4 * ff]);
                sa.y = fmul2(acc[4 * ff + 1], sd3[4 * ff + 1]);
                sb.x = fmul2(acc[4 * ff + 2], sd3[4 * ff + 2]);
                sb.y = fmul2(acc[4 * ff + 3], sd3[4 * ff + 3]);
                *reinterpret_cast<ull2*>(&cur[f0 + ff][qA])      = sa;
                *reinterpret_cast<ull2*>(&cur[f0 + ff][qA + 16]) = sb;
            }
        }
        __syncthreads();

        // ---- backward W3 -> dz2 ----
        {
            u64 acc[16];
#pragma unroll
            for (int q = 0; q < 16; q++) acc[q] = 0ULL;
            accum_bwd(w3, f0, cur, qA, acc);
            __syncthreads();
#pragma unroll
            for (int ff = 0; ff < 4; ff++) {
                ull2 sa, sb;
                sa.x = fmul2(acc[4 * ff],     sd2[4 * ff]);
                sa.y = fmul2(acc[4 * ff + 1], sd2[4 * ff + 1]);
                sb.x = fmul2(acc[4 * ff + 2], sd2[4 * ff + 2]);
                sb.y = fmul2(acc[4 * ff + 3], sd2[4 * ff + 3]);
                *reinterpret_cast<ull2*>(&cur[f0 + ff][qA])      = sa;
                *reinterpret_cast<ull2*>(&cur[f0 + ff][qA + 16]) = sb;
            }
        }
        __syncthreads();

        // ---- backward W2 -> dz1 (sd1 recomputed) ----
        {
            u64 acc[16];
#pragma unroll
            for (int q = 0; q < 16; q++) acc[q] = 0ULL;
            accum_bwd(w2, f0, cur, qA, acc);
            float4 wa = *reinterpret_cast<const float4*>(w1s + f0);
            float4 wb = *reinterpret_cast<const float4*>(w1s + 128 + f0);
            float4 bbq = *reinterpret_cast<const float4*>(b1s + f0);
            u64 xA0 = xs[qA],      xA1 = xs[qA + 1];
            u64 xB0 = xs[qA + 16], xB1 = xs[qA + 17];
            u64 yA0 = xs[32 + qA],      yA1 = xs[32 + qA + 1];
            u64 yB0 = xs[32 + qA + 16], yB1 = xs[32 + qA + 17];
            float wav[4] = {wa.x, wa.y, wa.z, wa.w};
            float wbv[4] = {wb.x, wb.y, wb.z, wb.w};
            float bbv[4] = {bbq.x, bbq.y, bbq.z, bbq.w};
            u64 dzv[16];
#pragma unroll
            for (int ff = 0; ff < 4; ff++) {
                u64 wap = pack2(wav[ff], wav[ff]);
                u64 wbp = pack2(wbv[ff], wbv[ff]);
                u64 bbp = pack2(bbv[ff], bbv[ff]);
                u64 zA0 = ffma2(xA0, wap, ffma2(yA0, wbp, bbp));
                u64 zA1 = ffma2(xA1, wap, ffma2(yA1, wbp, bbp));
                u64 zB0 = ffma2(xB0, wap, ffma2(yB0, wbp, bbp));
                u64 zB1 = ffma2(xB1, wap, ffma2(yB1, wbp, bbp));
                u64 h, d0, d1, d2, d3;
                silu2(zA0, h, d0);  silu2(zA1, h, d1);
                silu2(zB0, h, d2);  silu2(zB1, h, d3);
                dzv[4 * ff]     = fmul2(acc[4 * ff],     d0);
                dzv[4 * ff + 1] = fmul2(acc[4 * ff + 1], d1);
                dzv[4 * ff + 2] = fmul2(acc[4 * ff + 2], d2);
                dzv[4 * ff + 3] = fmul2(acc[4 * ff + 3], d3);
            }
            __syncthreads();
#pragma unroll
            for (int ff = 0; ff < 4; ff++) {
                ull2 sa; sa.x = dzv[4 * ff];     sa.y = dzv[4 * ff + 1];
                ull2 sb; sb.x = dzv[4 * ff + 2]; sb.y = dzv[4 * ff + 3];
                *reinterpret_cast<ull2*>(&cur[f0 + ff][qA])      = sa;
                *reinterpret_cast<ull2*>(&cur[f0 + ff][qA + 16]) = sb;
            }
        }
        __syncthreads();

        // ---- g = dz1 @ W1^T, clip, Langevin update ----
        {
            u64 g = 0ULL;
#pragma unroll
            for (int jj = 0; jj < 32; jj++) {
                int j = jp * 32 + jj;
                float w = w1s[ud * 128 + j];
                g = ffma2(cur[j][uq], pack2(w, w), g);
            }
            g = fadd2(g, __shfl_down_sync(0xffffffffu, g, 2, 4));
            g = fadd2(g, __shfl_down_sync(0xffffffffu, g, 1, 4));
            if (jp == 0) {
                float2 gv = unpack2(g);
                gv.x = fminf(fmaxf(gv.x, -0.03f), 0.03f);
                gv.y = fminf(fmaxf(gv.y, -0.03f), 0.03f);
                float2 xv = unpack2(xs[ud * 32 + uq]);
                float ax = xv.x + cn * nz0;  ax += eps * gv.x;
                float ay = xv.y + cn * nz1;  ay += eps * gv.y;
                ax = fminf(fmaxf(ax, -2.43f), 3.05f);
                ay = fminf(fmaxf(ay, -2.43f), 3.05f);
                xs[ud * 32 + uq] = pack2(ax, ay);
            }
        }
        __syncthreads();
    }

    // ---- write final x ----
    if (tid < 128) {
        int s = tid >> 1, d = tid & 1;
        float2 v = unpack2(xs[d * 32 + (s >> 1)]);
        out[(size_t)(s0 + s) * 2 + d] = (s & 1) ? v.y : v.x;
    }
}

extern "C" void kernel_launch(void* const* d_in, const int* in_sizes, int n_in,
                              void* d_out, int out_size) {
    const float* x0    = (const float*)d_in[0];
    const float* w1    = (const float*)d_in[1];
    const float* b1    = (const float*)d_in[2];
    const float* w2    = (const float*)d_in[3];
    const float* b2    = (const float*)d_in[4];
    const float* w3    = (const float*)d_in[5];
    const float* b3    = (const float*)d_in[6];
    const float* w4    = (const float*)d_in[7];
    const float* b4    = (const float*)d_in[8];
    const float* w5    = (const float*)d_in[9];
    const float* noise = (const float*)d_in[11];
    float* out = (float*)d_out;

    int nsamp = in_sizes[0] / 2;
    int nblocks = nsamp / SB;
    ebm_mcmc_kernel<<<nblocks, NTHR, SMEM_BYTES>>>(
        x0, w1, b1, w2, b2, w3, b3, w4, b4, w5, noise, out, nsamp);
}

// round 16
// speedup vs baseline: 1.3903x; 1.0314x over previous
#include <cuda_runtime.h>

#define HDIM   128
#define NSTEPS 60
#define SB     128     // samples per block (2 cohorts x 64)
#define NTHR   512
#define CPAD   32      // cur row length in u64 pairs

typedef unsigned long long u64;
typedef ulonglong2 ull2;

__device__ __forceinline__ u64 pack2(float a, float b) {
    u64 r; asm("mov.b64 %0, {%1, %2};" : "=l"(r) : "f"(a), "f"(b)); return r;
}
__device__ __forceinline__ float2 unpack2(u64 v) {
    float2 r; asm("mov.b64 {%0, %1}, %2;" : "=f"(r.x), "=f"(r.y) : "l"(v)); return r;
}
__device__ __forceinline__ u64 ffma2(u64 a, u64 b, u64 c) {
    u64 d; asm("fma.rn.f32x2 %0, %1, %2, %3;" : "=l"(d) : "l"(a), "l"(b), "l"(c)); return d;
}
__device__ __forceinline__ u64 fmul2(u64 a, u64 b) {
    u64 d; asm("mul.rn.f32x2 %0, %1, %2;" : "=l"(d) : "l"(a), "l"(b)); return d;
}
__device__ __forceinline__ u64 fadd2(u64 a, u64 b) {
    u64 d; asm("add.rn.f32x2 %0, %1, %2;" : "=l"(d) : "l"(a), "l"(b)); return d;
}
__device__ __forceinline__ void silu2(u64 z, u64& h, u64& d) {
    float2 zf = unpack2(z);
    float e0 = __expf(-zf.x), e1 = __expf(-zf.y);
    float s0 = 1.0f / (1.0f + e0), s1 = 1.0f / (1.0f + e1);
    float h0 = zf.x * s0,          h1 = zf.y * s1;
    float d0 = fmaf(h0, 1.0f - s0, s0);
    float d1 = fmaf(h1, 1.0f - s1, s1);
    h = pack2(h0, h1);
    d = pack2(d0, d1);
}

// cohort barrier (ids 1,2; 256 threads each)
#define BARC(coh) asm volatile("bar.sync %0, 256;" :: "r"((coh) + 1) : "memory")

// ---- SMEM-weight accumulators (R13-proven; swizzle (r,c) -> r*128 + (((c>>2)^(r&31))<<2)+(c&3)) ----
__device__ __forceinline__ void accum_fwd_s(const float* __restrict__ ws, int cc,
                                            const u64 (*__restrict__ cur)[CPAD],
                                            int qA, u64 acc[16]) {
#pragma unroll 4
    for (int k = 0; k < HDIM; k++) {
        const float4 w = *reinterpret_cast<const float4*>(
            ws + k * 128 + (((k & 31) ^ cc) << 2));
        ull2 hA = *reinterpret_cast<const ull2*>(&cur[k][qA]);
        ull2 hB = *reinterpret_cast<const ull2*>(&cur[k][qA + 16]);
        u64 wa = pack2(w.x, w.x), wb = pack2(w.y, w.y);
        u64 wc = pack2(w.z, w.z), wd = pack2(w.w, w.w);
        acc[0]  = ffma2(hA.x, wa, acc[0]);   acc[1]  = ffma2(hA.y, wa, acc[1]);
        acc[2]  = ffma2(hB.x, wa, acc[2]);   acc[3]  = ffma2(hB.y, wa, acc[3]);
        acc[4]  = ffma2(hA.x, wb, acc[4]);   acc[5]  = ffma2(hA.y, wb, acc[5]);
        acc[6]  = ffma2(hB.x, wb, acc[6]);   acc[7]  = ffma2(hB.y, wb, acc[7]);
        acc[8]  = ffma2(hA.x, wc, acc[8]);   acc[9]  = ffma2(hA.y, wc, acc[9]);
        acc[10] = ffma2(hB.x, wc, acc[10]);  acc[11] = ffma2(hB.y, wc, acc[11]);
        acc[12] = ffma2(hA.x, wd, acc[12]);  acc[13] = ffma2(hA.y, wd, acc[13]);
        acc[14] = ffma2(hB.x, wd, acc[14]);  acc[15] = ffma2(hB.y, wd, acc[15]);
    }
}

__device__ __forceinline__ void accum_bwd_s(const float* __restrict__ ws, int f0,
                                            const u64 (*__restrict__ cur)[CPAD],
                                            int qA, u64 acc[16]) {
    const float* r0b = ws + (f0 + 0) * 128;  const int x0m = (f0 + 0) & 31;
    const float* r1b = ws + (f0 + 1) * 128;  const int x1m = (f0 + 1) & 31;
    const float* r2b = ws + (f0 + 2) * 128;  const int x2m = (f0 + 2) & 31;
    const float* r3b = ws + (f0 + 3) * 128;  const int x3m = (f0 + 3) & 31;
#pragma unroll 4
    for (int k = 0; k < HDIM; k += 4) {
        int cc = k >> 2;
        float4 w0 = *reinterpret_cast<const float4*>(r0b + ((cc ^ x0m) << 2));
        float4 w1 = *reinterpret_cast<const float4*>(r1b + ((cc ^ x1m) << 2));
        float4 w2 = *reinterpret_cast<const float4*>(r2b + ((cc ^ x2m) << 2));
        float4 w3 = *reinterpret_cast<const float4*>(r3b + ((cc ^ x3m) << 2));
        ull2 hA0 = *reinterpret_cast<const ull2*>(&cur[k + 0][qA]);
        ull2 hA1 = *reinterpret_cast<const ull2*>(&cur[k + 1][qA]);
        ull2 hA2 = *reinterpret_cast<const ull2*>(&cur[k + 2][qA]);
        ull2 hA3 = *reinterpret_cast<const ull2*>(&cur[k + 3][qA]);
        ull2 hB0 = *reinterpret_cast<const ull2*>(&cur[k + 0][qA + 16]);
        ull2 hB1 = *reinterpret_cast<const ull2*>(&cur[k + 1][qA + 16]);
        ull2 hB2 = *reinterpret_cast<const ull2*>(&cur[k + 2][qA + 16]);
        ull2 hB3 = *reinterpret_cast<const ull2*>(&cur[k + 3][qA + 16]);
        u64 t;
        t = pack2(w0.x, w0.x);
        acc[0] = ffma2(hA0.x, t, acc[0]);  acc[1] = ffma2(hA0.y, t, acc[1]);
        acc[2] = ffma2(hB0.x, t, acc[2]);  acc[3] = ffma2(hB0.y, t, acc[3]);
        t = pack2(w0.y, w0.y);
        acc[0] = ffma2(hA1.x, t, acc[0]);  acc[1] = ffma2(hA1.y, t, acc[1]);
        acc[2] = ffma2(hB1.x, t, acc[2]);  acc[3] = ffma2(hB1.y, t, acc[3]);
        t = pack2(w0.z, w0.z);
        acc[0] = ffma2(hA2.x, t, acc[0]);  acc[1] = ffma2(hA2.y, t, acc[1]);
        acc[2] = ffma2(hB2.x, t, acc[2]);  acc[3] = ffma2(hB2.y, t, acc[3]);
        t = pack2(w0.w, w0.w);
        acc[0] = ffma2(hA3.x, t, acc[0]);  acc[1] = ffma2(hA3.y, t, acc[1]);
        acc[2] = ffma2(hB3.x, t, acc[2]);  acc[3] = ffma2(hB3.y, t, acc[3]);

        t = pack2(w1.x, w1.x);
        acc[4] = ffma2(hA0.x, t, acc[4]);  acc[5] = ffma2(hA0.y, t, acc[5]);
        acc[6] = ffma2(hB0.x, t, acc[6]);  acc[7] = ffma2(hB0.y, t, acc[7]);
        t = pack2(w1.y, w1.y);
        acc[4] = ffma2(hA1.x, t, acc[4]);  acc[5] = ffma2(hA1.y, t, acc[5]);
        acc[6] = ffma2(hB1.x, t, acc[6]);  acc[7] = ffma2(hB1.y, t, acc[7]);
        t = pack2(w1.z, w1.z);
        acc[4] = ffma2(hA2.x, t, acc[4]);  acc[5] = ffma2(hA2.y, t, acc[5]);
        acc[6] = ffma2(hB2.x, t, acc[6]);  acc[7] = ffma2(hB2.y, t, acc[7]);
        t = pack2(w1.w, w1.w);
        acc[4] = ffma2(hA3.x, t, acc[4]);  acc[5] = ffma2(hA3.y, t, acc[5]);
        acc[6] = ffma2(hB3.x, t, acc[6]);  acc[7] = ffma2(hB3.y, t, acc[7]);

        t = pack2(w2.x, w2.x);
        acc[8]  = ffma2(hA0.x, t, acc[8]);   acc[9]  = ffma2(hA0.y, t, acc[9]);
        acc[10] = ffma2(hB0.x, t, acc[10]);  acc[11] = ffma2(hB0.y, t, acc[11]);
        t = pack2(w2.y, w2.y);
        acc[8]  = ffma2(hA1.x, t, acc[8]);   acc[9]  = ffma2(hA1.y, t, acc[9]);
        acc[10] = ffma2(hB1.x, t, acc[10]);  acc[11] = ffma2(hB1.y, t, acc[11]);
        t = pack2(w2.z, w2.z);
        acc[8]  = ffma2(hA2.x, t, acc[8]);   acc[9]  = ffma2(hA2.y, t, acc[9]);
        acc[10] = ffma2(hB2.x, t, acc[10]);  acc[11] = ffma2(hB2.y, t, acc[11]);
        t = pack2(w2.w, w2.w);
        acc[8]  = ffma2(hA3.x, t, acc[8]);   acc[9]  = ffma2(hA3.y, t, acc[9]);
        acc[10] = ffma2(hB3.x, t, acc[10]);  acc[11] = ffma2(hB3.y, t, acc[11]);

        t = pack2(w3.x, w3.x);
        acc[12] = ffma2(hA0.x, t, acc[12]);  acc[13] = ffma2(hA0.y, t, acc[13]);
        acc[14] = ffma2(hB0.x, t, acc[14]);  acc[15] = ffma2(hB0.y, t, acc[15]);
        t = pack2(w3.y, w3.y);
        acc[12] = ffma2(hA1.x, t, acc[12]);  acc[13] = ffma2(hA1.y, t, acc[13]);
        acc[14] = ffma2(hB1.x, t, acc[14]);  acc[15] = ffma2(hB1.y, t, acc[15]);
        t = pack2(w3.z, w3.z);
        acc[12] = ffma2(hA2.x, t, acc[12]);  acc[13] = ffma2(hA2.y, t, acc[13]);
        acc[14] = ffma2(hB2.x, t, acc[14]);  acc[15] = ffma2(hB2.y, t, acc[15]);
        t = pack2(w3.w, w3.w);
        acc[12] = ffma2(hA3.x, t, acc[12]);  acc[13] = ffma2(hA3.y, t, acc[13]);
        acc[14] = ffma2(hB3.x, t, acc[14]);  acc[15] = ffma2(hB3.y, t, acc[15]);
    }
}

// ---- GLOBAL-weight accumulators (R15-proven; w4 is L2-resident) ----
__device__ __forceinline__ void accum_fwd_g(const float* __restrict__ wg, int f0,
                                            const u64 (*__restrict__ cur)[CPAD],
                                            int qA, u64 acc[16]) {
#pragma unroll 4
    for (int k = 0; k < HDIM; k++) {
        const float4 w = __ldg(reinterpret_cast<const float4*>(wg + k * 128 + f0));
        ull2 hA = *reinterpret_cast<const ull2*>(&cur[k][qA]);
        ull2 hB = *reinterpret_cast<const ull2*>(&cur[k][qA + 16]);
        u64 wa = pack2(w.x, w.x), wb = pack2(w.y, w.y);
        u64 wc = pack2(w.z, w.z), wd = pack2(w.w, w.w);
        acc[0]  = ffma2(hA.x, wa, acc[0]);   acc[1]  = ffma2(hA.y, wa, acc[1]);
        acc[2]  = ffma2(hB.x, wa, acc[2]);   acc[3]  = ffma2(hB.y, wa, acc[3]);
        acc[4]  = ffma2(hA.x, wb, acc[4]);   acc[5]  = ffma2(hA.y, wb, acc[5]);
        acc[6]  = ffma2(hB.x, wb, acc[6]);   acc[7]  = ffma2(hB.y, wb, acc[7]);
        acc[8]  = ffma2(hA.x, wc, acc[8]);   acc[9]  = ffma2(hA.y, wc, acc[9]);
        acc[10] = ffma2(hB.x, wc, acc[10]);  acc[11] = ffma2(hB.y, wc, acc[11]);
        acc[12] = ffma2(hA.x, wd, acc[12]);  acc[13] = ffma2(hA.y, wd, acc[13]);
        acc[14] = ffma2(hB.x, wd, acc[14]);  acc[15] = ffma2(hB.y, wd, acc[15]);
    }
}

__device__ __forceinline__ void accum_bwd_g(const float* __restrict__ wg, int f0,
                                            const u64 (*__restrict__ cur)[CPAD],
                                            int qA, u64 acc[16]) {
    const float* r0b = wg + (f0 + 0) * 128;
    const float* r1b = wg + (f0 + 1) * 128;
    const float* r2b = wg + (f0 + 2) * 128;
    const float* r3b = wg + (f0 + 3) * 128;
#pragma unroll 4
    for (int k = 0; k < HDIM; k += 4) {
        float4 w0 = __ldg(reinterpret_cast<const float4*>(r0b + k));
        float4 w1 = __ldg(reinterpret_cast<const float4*>(r1b + k));
        float4 w2 = __ldg(reinterpret_cast<const float4*>(r2b + k));
        float4 w3 = __ldg(reinterpret_cast<const float4*>(r3b + k));
        ull2 hA0 = *reinterpret_cast<const ull2*>(&cur[k + 0][qA]);
        ull2 hA1 = *reinterpret_cast<const ull2*>(&cur[k + 1][qA]);
        ull2 hA2 = *reinterpret_cast<const ull2*>(&cur[k + 2][qA]);
        ull2 hA3 = *reinterpret_cast<const ull2*>(&cur[k + 3][qA]);
        ull2 hB0 = *reinterpret_cast<const ull2*>(&cur[k + 0][qA + 16]);
        ull2 hB1 = *reinterpret_cast<const ull2*>(&cur[k + 1][qA + 16]);
        ull2 hB2 = *reinterpret_cast<const ull2*>(&cur[k + 2][qA + 16]);
        ull2 hB3 = *reinterpret_cast<const ull2*>(&cur[k + 3][qA + 16]);
        u64 t;
        t = pack2(w0.x, w0.x);
        acc[0] = ffma2(hA0.x, t, acc[0]);  acc[1] = ffma2(hA0.y, t, acc[1]);
        acc[2] = ffma2(hB0.x, t, acc[2]);  acc[3] = ffma2(hB0.y, t, acc[3]);
        t = pack2(w0.y, w0.y);
        acc[0] = ffma2(hA1.x, t, acc[0]);  acc[1] = ffma2(hA1.y, t, acc[1]);
        acc[2] = ffma2(hB1.x, t, acc[2]);  acc[3] = ffma2(hB1.y, t, acc[3]);
        t = pack2(w0.z, w0.z);
        acc[0] = ffma2(hA2.x, t, acc[0]);  acc[1] = ffma2(hA2.y, t, acc[1]);
        acc[2] = ffma2(hB2.x, t, acc[2]);  acc[3] = ffma2(hB2.y, t, acc[3]);
        t = pack2(w0.w, w0.w);
        acc[0] = ffma2(hA3.x, t, acc[0]);  acc[1] = ffma2(hA3.y, t, acc[1]);
        acc[2] = ffma2(hB3.x, t, acc[2]);  acc[3] = ffma2(hB3.y, t, acc[3]);

        t = pack2(w1.x, w1.x);
        acc[4] = ffma2(hA0.x, t, acc[4]);  acc[5] = ffma2(hA0.y, t, acc[5]);
        acc[6] = ffma2(hB0.x, t, acc[6]);  acc[7] = ffma2(hB0.y, t, acc[7]);
        t = pack2(w1.y, w1.y);
        acc[4] = ffma2(hA1.x, t, acc[4]);  acc[5] = ffma2(hA1.y, t, acc[5]);
        acc[6] = ffma2(hB1.x, t, acc[6]);  acc[7] = ffma2(hB1.y, t, acc[7]);
        t = pack2(w1.z, w1.z);
        acc[4] = ffma2(hA2.x, t, acc[4]);  acc[5] = ffma2(hA2.y, t, acc[5]);
        acc[6] = ffma2(hB2.x, t, acc[6]);  acc[7] = ffma2(hB2.y, t, acc[7]);
        t = pack2(w1.w, w1.w);
        acc[4] = ffma2(hA3.x, t, acc[4]);  acc[5] = ffma2(hA3.y, t, acc[5]);
        acc[6] = ffma2(hB3.x, t, acc[6]);  acc[7] = ffma2(hB3.y, t, acc[7]);

        t = pack2(w2.x, w2.x);
        acc[8]  = ffma2(hA0.x, t, acc[8]);   acc[9]  = ffma2(hA0.y, t, acc[9]);
        acc[10] = ffma2(hB0.x, t, acc[10]);  acc[11] = ffma2(hB0.y, t, acc[11]);
        t = pack2(w2.y, w2.y);
        acc[8]  = ffma2(hA1.x, t, acc[8]);   acc[9]  = ffma2(hA1.y, t, acc[9]);
        acc[10] = ffma2(hB1.x, t, acc[10]);  acc[11] = ffma2(hB1.y, t, acc[11]);
        t = pack2(w2.z, w2.z);
        acc[8]  = ffma2(hA2.x, t, acc[8]);   acc[9]  = ffma2(hA2.y, t, acc[9]);
        acc[10] = ffma2(hB2.x, t, acc[10]);  acc[11] = ffma2(hB2.y, t, acc[11]);
        t = pack2(w2.w, w2.w);
        acc[8]  = ffma2(hA3.x, t, acc[8]);   acc[9]  = ffma2(hA3.y, t, acc[9]);
        acc[10] = ffma2(hB3.x, t, acc[10]);  acc[11] = ffma2(hB3.y, t, acc[11]);

        t = pack2(w3.x, w3.x);
        acc[12] = ffma2(hA0.x, t, acc[12]);  acc[13] = ffma2(hA0.y, t, acc[13]);
        acc[14] = ffma2(hB0.x, t, acc[14]);  acc[15] = ffma2(hB0.y, t, acc[15]);
        t = pack2(w3.y, w3.y);
        acc[12] = ffma2(hA1.x, t, acc[12]);  acc[13] = ffma2(hA1.y, t, acc[13]);
        acc[14] = ffma2(hB1.x, t, acc[14]);  acc[15] = ffma2(hB1.y, t, acc[15]);
        t = pack2(w3.z, w3.z);
        acc[12] = ffma2(hA2.x, t, acc[12]);  acc[13] = ffma2(hA2.y, t, acc[13]);
        acc[14] = ffma2(hB2.x, t, acc[14]);  acc[15] = ffma2(hB2.y, t, acc[15]);
        t = pack2(w3.w, w3.w);
        acc[12] = ffma2(hA3.x, t, acc[12]);  acc[13] = ffma2(hA3.y, t, acc[13]);
        acc[14] = ffma2(hB3.x, t, acc[14]);  acc[15] = ffma2(hB3.y, t, acc[15]);
    }
}

// SMEM (bytes): cur 0 (2x32768) | w2s 65536 | w3s 131072 | w1s 196608 (1024)
//   b1s 197632 | b2s 198144 | b3s 198656 | b4s 199168 | w5s 199680 | xs 200192 (1024)
#define SMEM_BYTES 201216

__global__ void __launch_bounds__(NTHR, 1)
ebm_mcmc_kernel(const float* __restrict__ x0,
                const float* __restrict__ w1, const float* __restrict__ b1,
                const float* __restrict__ w2, const float* __restrict__ b2,
                const float* __restrict__ w3, const float* __restrict__ b3,
                const float* __restrict__ w4, const float* __restrict__ b4,
                const float* __restrict__ w5,
                const float* __restrict__ noise,
                float* __restrict__ out, int nsamp) {
    extern __shared__ unsigned char smraw[];
    float* w2s = reinterpret_cast<float*>(smraw + 65536);
    float* w3s = reinterpret_cast<float*>(smraw + 131072);
    float* w1s = reinterpret_cast<float*>(smraw + 196608);  // [2][128]
    float* b1s = w1s + 256;
    float* b2s = b1s + 128;
    float* b3s = b2s + 128;
    float* b4s = b3s + 128;
    float* w5s = b4s + 128;
    u64*   xsa = reinterpret_cast<u64*>(w5s + 128);         // [2][64]

    const int tid  = threadIdx.x;
    const int coh  = tid >> 8;        // cohort 0/1
    const int ctid = tid & 255;
    u64 (*cur)[CPAD] = reinterpret_cast<u64(*)[CPAD]>(smraw + coh * 32768);
    u64* xs = xsa + coh * 64;

    const int f0  = (ctid >> 3) * 4;  // 4 contiguous output features
    const int cc0 = f0 >> 2;
    const int qA  = (ctid & 7) * 2;   // pairs qA,qA+1 and qA+16,qA+17
    const int s0  = blockIdx.x * SB + coh * 64;

    // ---- load shared weights (all 512 threads) ----
    for (int idx = tid; idx < HDIM * HDIM; idx += NTHR) {
        int r = idx >> 7, c = idx & 127;
        int o = r * 128 + ((((c >> 2) ^ (r & 31)) << 2) | (c & 3));
        w2s[o] = w2[idx];
        w3s[o] = w3[idx];
    }
    if (tid < 256) w1s[tid] = w1[tid];
    if (tid < 128) {
        b1s[tid] = b1[tid];
        b2s[tid] = b2[tid];
        b3s[tid] = b3[tid];
        b4s[tid] = b4[tid];
        w5s[tid] = w5[tid];
    }
    if (tid < 128) {
        int c2 = tid >> 6, d = (tid >> 5) & 1, p = tid & 31;
        size_t bx = (size_t)(blockIdx.x * SB + c2 * 64 + 2 * p) * 2 + d;
        xsa[c2 * 64 + d * 32 + p] = pack2(x0[bx], x0[bx + 2]);
    }
    __syncthreads();

    // silu' for layers 2,3 (16 each); sd1 recomputed; sd4 transient
    u64 sd2[16], sd3[16];

    // update-phase mapping: jp width 4 (32 j each)
    const int jp = ctid & 3;
    const int ug = ctid >> 2;      // 0..63
    const int ud = ug >> 5;        // dim
    const int uq = ug & 31;        // pair

    for (int i = 0; i < NSTEPS; i++) {
        float eps = 10.0f * (1.0f - (float)i / 60.0f);
        float cn  = sqrtf(2.0f * eps) * 0.005f;

        float nz0 = 0.0f, nz1 = 0.0f;
        if (jp == 0) {
            size_t base = ((size_t)i * nsamp + s0 + 2 * uq) * 2 + ud;
            nz0 = noise[base];
            nz1 = noise[base + 2];
        }

        // ---- forward L1 ----
        {
            float4 wa = *reinterpret_cast<const float4*>(w1s + f0);
            float4 wb = *reinterpret_cast<const float4*>(w1s + 128 + f0);
            float4 bbq = *reinterpret_cast<const float4*>(b1s + f0);
            u64 xA0 = xs[qA],      xA1 = xs[qA + 1];
            u64 xB0 = xs[qA + 16], xB1 = xs[qA + 17];
            u64 yA0 = xs[32 + qA],      yA1 = xs[32 + qA + 1];
            u64 yB0 = xs[32 + qA + 16], yB1 = xs[32 + qA + 17];
            float wav[4] = {wa.x, wa.y, wa.z, wa.w};
            float wbv[4] = {wb.x, wb.y, wb.z, wb.w};
            float bbv[4] = {bbq.x, bbq.y, bbq.z, bbq.w};
#pragma unroll
            for (int ff = 0; ff < 4; ff++) {
                u64 wap = pack2(wav[ff], wav[ff]);
                u64 wbp = pack2(wbv[ff], wbv[ff]);
                u64 bbp = pack2(bbv[ff], bbv[ff]);
                u64 zA0 = ffma2(xA0, wap, ffma2(yA0, wbp, bbp));
                u64 zA1 = ffma2(xA1, wap, ffma2(yA1, wbp, bbp));
                u64 zB0 = ffma2(xB0, wap, ffma2(yB0, wbp, bbp));
                u64 zB1 = ffma2(xB1, wap, ffma2(yB1, wbp, bbp));
                u64 hA0, hA1, hB0, hB1, du;
                silu2(zA0, hA0, du);  silu2(zA1, hA1, du);
                silu2(zB0, hB0, du);  silu2(zB1, hB1, du);
                ull2 sa; sa.x = hA0; sa.y = hA1;
                ull2 sb; sb.x = hB0; sb.y = hB1;
                *reinterpret_cast<ull2*>(&cur[f0 + ff][qA])      = sa;
                *reinterpret_cast<ull2*>(&cur[f0 + ff][qA + 16]) = sb;
            }
        }
        BARC(coh);

        // ---- forward L2 (SMEM weights) ----
        {
            u64 acc[16];
            float4 bb = *reinterpret_cast<const float4*>(b2s + f0);
            float bbv[4] = {bb.x, bb.y, bb.z, bb.w};
#pragma unroll
            for (int ff = 0; ff < 4; ff++) {
                u64 bp = pack2(bbv[ff], bbv[ff]);
                acc[4 * ff] = acc[4 * ff + 1] = acc[4 * ff + 2] = acc[4 * ff + 3] = bp;
            }
            accum_fwd_s(w2s, cc0, cur, qA, acc);
            BARC(coh);
#pragma unroll
            for (int ff = 0; ff < 4; ff++) {
                u64 hA0, hA1, hB0, hB1;
                silu2(acc[4 * ff],     hA0, sd2[4 * ff]);
                silu2(acc[4 * ff + 1], hA1, sd2[4 * ff + 1]);
                silu2(acc[4 * ff + 2], hB0, sd2[4 * ff + 2]);
                silu2(acc[4 * ff + 3], hB1, sd2[4 * ff + 3]);
                ull2 sa; sa.x = hA0; sa.y = hA1;
                ull2 sb; sb.x = hB0; sb.y = hB1;
                *reinterpret_cast<ull2*>(&cur[f0 + ff][qA])      = sa;
                *reinterpret_cast<ull2*>(&cur[f0 + ff][qA + 16]) = sb;
            }
        }
        BARC(coh);

        // ---- forward L3 (SMEM weights) ----
        {
            u64 acc[16];
            float4 bb = *reinterpret_cast<const float4*>(b3s + f0);
            float bbv[4] = {bb.x, bb.y, bb.z, bb.w};
#pragma unroll
            for (int ff = 0; ff < 4; ff++) {
                u64 bp = pack2(bbv[ff], bbv[ff]);
                acc[4 * ff] = acc[4 * ff + 1] = acc[4 * ff + 2] = acc[4 * ff + 3] = bp;
            }
            accum_fwd_s(w3s, cc0, cur, qA, acc);
            BARC(coh);
#pragma unroll
            for (int ff = 0; ff < 4; ff++) {
                u64 hA0, hA1, hB0, hB1;
                silu2(acc[4 * ff],     hA0, sd3[4 * ff]);
                silu2(acc[4 * ff + 1], hA1, sd3[4 * ff + 1]);
                silu2(acc[4 * ff + 2], hB0, sd3[4 * ff + 2]);
                silu2(acc[4 * ff + 3], hB1, sd3[4 * ff + 3]);
                ull2 sa; sa.x = hA0; sa.y = hA1;
                ull2 sb; sb.x = hB0; sb.y = hB1;
                *reinterpret_cast<ull2*>(&cur[f0 + ff][qA])      = sa;
                *reinterpret_cast<ull2*>(&cur[f0 + ff][qA + 16]) = sb;
            }
        }
        BARC(coh);

        // ---- forward L4 (GLOBAL w4; h4 dead) + seed dz4 = w5 .* silu'(z4) ----
        {
            u64 acc[16];
            float4 bb = *reinterpret_cast<const float4*>(b4s + f0);
            float bbv[4] = {bb.x, bb.y, bb.z, bb.w};
#pragma unroll
            for (int ff = 0; ff < 4; ff++) {
                u64 bp = pack2(bbv[ff], bbv[ff]);
                acc[4 * ff] = acc[4 * ff + 1] = acc[4 * ff + 2] = acc[4 * ff + 3] = bp;
            }
            accum_fwd_g(w4, f0, cur, qA, acc);
            float4 w5q = *reinterpret_cast<const float4*>(w5s + f0);
            float w5a[4] = {w5q.x, w5q.y, w5q.z, w5q.w};
            u64 dz[16];
#pragma unroll
            for (int ff = 0; ff < 4; ff++) {
                u64 h, d0, d1, d2, d3;
                silu2(acc[4 * ff],     h, d0);
                silu2(acc[4 * ff + 1], h, d1);
                silu2(acc[4 * ff + 2], h, d2);
                silu2(acc[4 * ff + 3], h, d3);
                u64 wp = pack2(w5a[ff], w5a[ff]);
                dz[4 * ff]     = fmul2(wp, d0);
                dz[4 * ff + 1] = fmul2(wp, d1);
                dz[4 * ff + 2] = fmul2(wp, d2);
                dz[4 * ff + 3] = fmul2(wp, d3);
            }
            BARC(coh);   // all reads of h3 done
#pragma unroll
            for (int ff = 0; ff < 4; ff++) {
                ull2 sa; sa.x = dz[4 * ff];     sa.y = dz[4 * ff + 1];
                ull2 sb; sb.x = dz[4 * ff + 2]; sb.y = dz[4 * ff + 3];
                *reinterpret_cast<ull2*>(&cur[f0 + ff][qA])      = sa;
                *reinterpret_cast<ull2*>(&cur[f0 + ff][qA + 16]) = sb;
            }
        }
        BARC(coh);

        // ---- backward W4 (GLOBAL) -> dz3 ----
        {
            u64 acc[16];
#pragma unroll
            for (int q = 0; q < 16; q++) acc[q] = 0ULL;
            accum_bwd_g(w4, f0, cur, qA, acc);
            BARC(coh);
#pragma unroll
            for (int ff = 0; ff < 4; ff++) {
                ull2 sa, sb;
                sa.x = fmul2(acc[4 * ff],     sd3[4 * ff]);
                sa.y = fmul2(acc[4 * ff + 1], sd3[4 * ff + 1]);
                sb.x = fmul2(acc[4 * ff + 2], sd3[4 * ff + 2]);
                sb.y = fmul2(acc[4 * ff + 3], sd3[4 * ff + 3]);
                *reinterpret_cast<ull2*>(&cur[f0 + ff][qA])      = sa;
                *reinterpret_cast<ull2*>(&cur[f0 + ff][qA + 16]) = sb;
            }
        }
        BARC(coh);

        // ---- backward W3 (SMEM) -> dz2 ----
        {
            u64 acc[16];
#pragma unroll
            for (int q = 0; q < 16; q++) acc[q] = 0ULL;
            accum_bwd_s(w3s, f0, cur, qA, acc);
            BARC(coh);
#pragma unroll
            for (int ff = 0; ff < 4; ff++) {
                ull2 sa, sb;
                sa.x = fmul2(acc[4 * ff],     sd2[4 * ff]);
                sa.y = fmul2(acc[4 * ff + 1], sd2[4 * ff + 1]);
                sb.x = fmul2(acc[4 * ff + 2], sd2[4 * ff + 2]);
                sb.y = fmul2(acc[4 * ff + 3], sd2[4 * ff + 3]);
                *reinterpret_cast<ull2*>(&cur[f0 + ff][qA])      = sa;
                *reinterpret_cast<ull2*>(&cur[f0 + ff][qA + 16]) = sb;
            }
        }
        BARC(coh);

        // ---- backward W2 (SMEM) -> dz1 (sd1 recomputed) ----
        {
            u64 acc[16];
#pragma unroll
            for (int q = 0; q < 16; q++) acc[q] = 0ULL;
            accum_bwd_s(w2s, f0, cur, qA, acc);
            float4 wa = *reinterpret_cast<const float4*>(w1s + f0);
            float4 wb = *reinterpret_cast<const float4*>(w1s + 128 + f0);
            float4 bbq = *reinterpret_cast<const float4*>(b1s + f0);
            u64 xA0 = xs[qA],      xA1 = xs[qA + 1];
            u64 xB0 = xs[qA + 16], xB1 = xs[qA + 17];
            u64 yA0 = xs[32 + qA],      yA1 = xs[32 + qA + 1];
            u64 yB0 = xs[32 + qA + 16], yB1 = xs[32 + qA + 17];
            float wav[4] = {wa.x, wa.y, wa.z, wa.w};
            float wbv[4] = {wb.x, wb.y, wb.z, wb.w};
            float bbv[4] = {bbq.x, bbq.y, bbq.z, bbq.w};
            u64 dzv[16];
#pragma unroll
            for (int ff = 0; ff < 4; ff++) {
                u64 wap = pack2(wav[ff], wav[ff]);
                u64 wbp = pack2(wbv[ff], wbv[ff]);
                u64 bbp = pack2(bbv[ff], bbv[ff]);
                u64 zA0 = ffma2(xA0, wap, ffma2(yA0, wbp, bbp));
                u64 zA1 = ffma2(xA1, wap, ffma2(yA1, wbp, bbp));
                u64 zB0 = ffma2(xB0, wap, ffma2(yB0, wbp, bbp));
                u64 zB1 = ffma2(xB1, wap, ffma2(yB1, wbp, bbp));
                u64 h, d0, d1, d2, d3;
                silu2(zA0, h, d0);  silu2(zA1, h, d1);
                silu2(zB0, h, d2);  silu2(zB1, h, d3);
                dzv[4 * ff]     = fmul2(acc[4 * ff],     d0);
                dzv[4 * ff + 1] = fmul2(acc[4 * ff + 1], d1);
                dzv[4 * ff + 2] = fmul2(acc[4 * ff + 2], d2);
                dzv[4 * ff + 3] = fmul2(acc[4 * ff + 3], d3);
            }
            BARC(coh);
#pragma unroll
            for (int ff = 0; ff < 4; ff++) {
                ull2 sa; sa.x = dzv[4 * ff];     sa.y = dzv[4 * ff + 1];
                ull2 sb; sb.x = dzv[4 * ff + 2]; sb.y = dzv[4 * ff + 3];
                *reinterpret_cast<ull2*>(&cur[f0 + ff][qA])      = sa;
                *reinterpret_cast<ull2*>(&cur[f0 + ff][qA + 16]) = sb;
            }
        }
        BARC(coh);

        // ---- g = dz1 @ W1^T, clip, Langevin update ----
        {
            u64 g = 0ULL;
#pragma unroll
            for (int jj = 0; jj < 32; jj++) {
                int j = jp * 32 + jj;
                float w = w1s[ud * 128 + j];
                g = ffma2(cur[j][uq], pack2(w, w), g);
            }
            g = fadd2(g, __shfl_down_sync(0xffffffffu, g, 2, 4));
            g = fadd2(g, __shfl_down_sync(0xffffffffu, g, 1, 4));
            if (jp == 0) {
                float2 gv = unpack2(g);
                gv.x = fminf(fmaxf(gv.x, -0.03f), 0.03f);
                gv.y = fminf(fmaxf(gv.y, -0.03f), 0.03f);
                float2 xv = unpack2(xs[ud * 32 + uq]);
                float ax = xv.x + cn * nz0;  ax += eps * gv.x;
                float ay = xv.y + cn * nz1;  ay += eps * gv.y;
                ax = fminf(fmaxf(ax, -2.43f), 3.05f);
                ay = fminf(fmaxf(ay, -2.43f), 3.05f);
                xs[ud * 32 + uq] = pack2(ax, ay);
            }
        }
        BARC(coh);
    }

    // ---- write final x (per cohort) ----
    if (ctid < 128) {
        int s = ctid >> 1, d = ctid & 1;
        float2 v = unpack2(xs[d * 32 + (s >> 1)]);
        out[(size_t)(s0 + s) * 2 + d] = (s & 1) ? v.y : v.x;
    }
}

extern "C" void kernel_launch(void* const* d_in, const int* in_sizes, int n_in,
                              void* d_out, int out_size) {
    const float* x0    = (const float*)d_in[0];
    const float* w1    = (const float*)d_in[1];
    const float* b1    = (const float*)d_in[2];
    const float* w2    = (const float*)d_in[3];
    const float* b2    = (const float*)d_in[4];
    const float* w3    = (const float*)d_in[5];
    const float* b3    = (const float*)d_in[6];
    const float* w4    = (const float*)d_in[7];
    const float* b4    = (const float*)d_in[8];
    const float* w5    = (const float*)d_in[9];
    const float* noise = (const float*)d_in[11];
    float* out = (float*)d_out;

    int nsamp = in_sizes[0] / 2;
    cudaFuncSetAttribute(ebm_mcmc_kernel,
                         cudaFuncAttributeMaxDynamicSharedMemorySize, SMEM_BYTES);
    int nblocks = nsamp / SB;
    ebm_mcmc_kernel<<<nblocks, NTHR, SMEM_BYTES>>>(
        x0, w1, b1, w2, b2, w3, b3, w4, b4, w5, noise, out, nsamp);
}